// round 15
// baseline (speedup 1.0000x reference)
#include <cuda_runtime.h>
#include <cuda_fp16.h>
#include <cstdint>
#include <math.h>

// ---------------- problem constants ----------------
#define BATCH 4
#define CDIM  384
#define HDIM  128
#define WDIM  128
#define HWPIX 16384
#define NPIX  65536
#define HEADS 12
#define HD    32
#define WS    8
#define NTOK  64
#define NWIN  1024
#define QKVC  1152

// ---------------- device scratch ----------------
// g_qkvh layout: per pixel, head-interleaved: [head][q(32) k(32) v(32)]
__device__ __half g_qkvh[(size_t)NPIX * QKVC];
__device__ __half g_aoh[(size_t)NPIX * CDIM];
__device__ __half g_xTh[(size_t)NPIX * CDIM];
__device__ __half g_wbh[QKVC * CDIM];
__device__ float  g_bqkv[QKVC];
__device__ float  g_bias[HEADS * 225];
__device__ __half g_Wch[CDIM * CDIM];

// ---------------- helpers ----------------
__device__ __forceinline__ uint32_t smem_u32(const void* p) {
    uint32_t a;
    asm("{ .reg .u64 t; cvta.to.shared.u64 t, %1; cvt.u32.u64 %0, t; }" : "=r"(a) : "l"(p));
    return a;
}
__device__ __forceinline__ void cp16(uint32_t saddr, const void* g) {
    asm volatile("cp.async.cg.shared.global [%0], [%1], 16;" :: "r"(saddr), "l"(g));
}
#define CP_COMMIT() asm volatile("cp.async.commit_group;" ::: "memory")
#define CP_WAIT0()  asm volatile("cp.async.wait_group 0;" ::: "memory")
#define CP_WAIT1()  asm volatile("cp.async.wait_group 1;" ::: "memory")

__device__ __forceinline__ void ldm4(uint32_t* r, uint32_t addr) {
    asm volatile("ldmatrix.sync.aligned.m8n8.x4.shared.b16 {%0,%1,%2,%3}, [%4];"
        : "=r"(r[0]), "=r"(r[1]), "=r"(r[2]), "=r"(r[3]) : "r"(addr));
}

__device__ __forceinline__ void mma16(float* c, const uint32_t* a, const uint32_t* b) {
    asm volatile(
        "mma.sync.aligned.m16n8k16.row.col.f32.f16.f16.f32 "
        "{%0,%1,%2,%3}, {%4,%5,%6,%7}, {%8,%9}, {%0,%1,%2,%3};"
        : "+f"(c[0]), "+f"(c[1]), "+f"(c[2]), "+f"(c[3])
        : "r"(a[0]), "r"(a[1]), "r"(a[2]), "r"(a[3]),
          "r"(b[0]), "r"(b[1]));
}

// =================================================================
// unified prep kernel: xpose | wprep | wc | bias, 256 threads
// =================================================================
#define NB_XPOSE (512 * 12 * 4)
#define NB_WPREP ((QKVC * CDIM) / 256)
#define NB_WC    ((CDIM * CDIM) / 256)
#define NB_BIAS  225
#define NB_PREP  (NB_XPOSE + NB_WPREP + NB_WC + NB_BIAS)

__global__ void __launch_bounds__(256) prep_kernel(
        const float* __restrict__ x,
        const float* __restrict__ w_qk, const float* __restrict__ b_qk,
        const float* __restrict__ w_v,  const float* __restrict__ b_v,
        const float* __restrict__ w_proj, const float* __restrict__ w_po,
        const float* __restrict__ pcw, const float* __restrict__ psc,
        const float* __restrict__ mw1, const float* __restrict__ mb1,
        const float* __restrict__ mw2, const float* __restrict__ mb2) {
    __shared__ __align__(16) float tile[32][33];
    __shared__ __align__(16) float rel[CDIM];
    __shared__ __align__(16) float hid[128];
    __shared__ float part[256];
    int blk = blockIdx.x;
    int t = threadIdx.x;

    if (blk < NB_XPOSE) {
        int bx = blk & 511, by = (blk >> 9) % 12, bz = blk / (512 * 12);
        int tx = t & 31, ty = t >> 5;
        const float* src = x + ((size_t)(bz * CDIM + by * 32)) * HWPIX + bx * 32;
        #pragma unroll
        for (int i = 0; i < 32; i += 8)
            tile[ty + i][tx] = src[(size_t)(ty + i) * HWPIX + tx];
        __syncthreads();
        __half* dst = g_xTh + ((size_t)(bz * HWPIX + bx * 32)) * CDIM + by * 32;
        #pragma unroll
        for (int i = 0; i < 32; i += 8)
            dst[(size_t)(ty + i) * CDIM + tx] = __float2half_rn(tile[tx][ty + i]);
        return;
    }
    blk -= NB_XPOSE;
    if (blk < NB_WPREP) {
        int i = blk * 256 + t;
        float v = (i < 2 * CDIM * CDIM) ? w_qk[i] : w_v[i - 2 * CDIM * CDIM];
        g_wbh[i] = __float2half_rn(v);
        if (i < QKVC)
            g_bqkv[i] = (i < 2 * CDIM) ? b_qk[i] : b_v[i - 2 * CDIM];
        return;
    }
    blk -= NB_WPREP;
    if (blk < NB_WC) {
        int idx = blk * 256 + t;
        int o = idx / CDIM, c = idx - o * CDIM;
        const float* pr = w_proj + o * CDIM;
        float a0 = 0.f, a1 = 0.f, a2 = 0.f, a3 = 0.f;
        for (int k = 0; k < CDIM; k += 4) {
            a0 += pr[k] * w_po[k * CDIM + c];
            a1 += pr[k + 1] * w_po[(k + 1) * CDIM + c];
            a2 += pr[k + 2] * w_po[(k + 2) * CDIM + c];
            a3 += pr[k + 3] * w_po[(k + 3) * CDIM + c];
        }
        g_Wch[o * CDIM + c] = __float2half_rn((a0 + a1) + (a2 + a3));
        return;
    }
    blk -= NB_WC;
    {
        int idx = blk;
        float dx = (float)((idx % 15) - 7) * (2.0f / 7.0f);
        float dy = (float)((idx / 15) - 7) * (2.0f / 7.0f);
        int u = t & 127, hv2 = t >> 7;
        float sc = psc[0];
        for (int c = t; c < CDIM; c += 256)
            rel[c] = sc * (pcw[2 * c] * dx + pcw[2 * c + 1] * dy);
        __syncthreads();
        {
            float a0 = 0.f, a1 = 0.f, a2 = 0.f, a3 = 0.f;
            const float4* w = (const float4*)(mw1 + u * CDIM + hv2 * 192);
            const float4* r = (const float4*)(rel + hv2 * 192);
            #pragma unroll 4
            for (int c = 0; c < 48; c++) {
                float4 wv = w[c], rv = r[c];
                a0 += wv.x * rv.x; a1 += wv.y * rv.y;
                a2 += wv.z * rv.z; a3 += wv.w * rv.w;
            }
            part[t] = (a0 + a1) + (a2 + a3);
        }
        __syncthreads();
        if (t < 128) {
            float s = mb1[t] + part[t] + part[t + 128];
            hid[t] = 0.5f * s * (1.0f + erff(s * 0.70710678118654752f));
        }
        __syncthreads();
        if (t < HEADS) {
            float a0 = 0.f, a1 = 0.f, a2 = 0.f, a3 = 0.f;
            const float4* w2 = (const float4*)(mw2 + t * 128);
            const float4* hh = (const float4*)hid;
            #pragma unroll 4
            for (int j = 0; j < 32; j++) {
                float4 wv = w2[j], hvv = hh[j];
                a0 += wv.x * hvv.x; a1 += wv.y * hvv.y;
                a2 += wv.z * hvv.z; a3 += wv.w * hvv.w;
            }
            g_bias[t * 225 + idx] = mb2[t] + (a0 + a1) + (a2 + a3);
        }
    }
}

// =================================================================
// fp16 mma.sync GEMM with ldmatrix, 3-stage cp.async pipeline
// MODE 0 writes head-interleaved qkv layout
// =================================================================
#define HP     72
#define KCH    64
#define NCH    6
#define NSTAGE 3
#define STAGE_H (2 * 128 * HP)
#define GEMM_SMEM (NSTAGE * STAGE_H * 2)

template <int MODE>
__global__ void __launch_bounds__(256) gemm_mma(
        const __half* __restrict__ Aptr, const __half* __restrict__ Bptr,
        const float* __restrict__ biasptr, void* __restrict__ outp) {
    extern __shared__ __align__(16) __half smh[];

    int tid = threadIdx.x;
    int n0 = blockIdx.x * 128;
    int m0 = blockIdx.y * 128;
    int lane = tid & 31, wid = tid >> 5;
    int wm = (wid & 3) * 32;
    int wn = (wid >> 2) * 64;

    const __half* Arow = Aptr + (size_t)m0 * CDIM;
    const __half* Brow = Bptr + (size_t)n0 * CDIM;
    uint32_t aU[NSTAGE], bU[NSTAGE];
    #pragma unroll
    for (int s = 0; s < NSTAGE; s++) {
        aU[s] = smem_u32(smh + s * STAGE_H);
        bU[s] = smem_u32(smh + s * STAGE_H + 128 * HP);
    }

    int ldrow = tid >> 3, ldseg = tid & 7;
    auto load_chunk = [&](int k0, int s) {
        #pragma unroll
        for (int i = 0; i < 4; i++) {
            int row = ldrow + i * 32;
            uint32_t so = (uint32_t)(row * HP + ldseg * 8) * 2;
            cp16(aU[s] + so, Arow + (size_t)row * CDIM + k0 + ldseg * 8);
            cp16(bU[s] + so, Brow + (size_t)row * CDIM + k0 + ldseg * 8);
        }
        CP_COMMIT();
    };

    float acc[2][8][4];
    #pragma unroll
    for (int mt = 0; mt < 2; mt++)
        #pragma unroll
        for (int nt = 0; nt < 8; nt++)
            #pragma unroll
            for (int j = 0; j < 4; j++) acc[mt][nt][j] = 0.f;

    load_chunk(0, 0);
    load_chunk(KCH, 1);

    int lr = lane & 7, g = lane >> 3;
    int arow[2];
    arow[0] = wm + (g & 1) * 8 + lr;
    arow[1] = wm + 16 + (g & 1) * 8 + lr;
    int akoff = (g >> 1) * 8;
    int brow[4];
    #pragma unroll
    for (int q = 0; q < 4; q++)
        brow[q] = wn + (2 * q + (g >> 1)) * 8 + lr;
    int bkoff = (g & 1) * 8;

    int r4 = lane >> 2, c4 = lane & 3;
    for (int i = 0; i < NCH; i++) {
        if (i + 1 < NCH) CP_WAIT1(); else CP_WAIT0();
        __syncthreads();
        if (i + 2 < NCH) load_chunk((i + 2) * KCH, (i + 2) % NSTAGE);
        int s = i % NSTAGE;
        uint32_t aBase = aU[s];
        uint32_t bBase = bU[s];
        #pragma unroll
        for (int kk = 0; kk < 4; kk++) {
            int kb = kk * 16;
            uint32_t a[2][4];
            #pragma unroll
            for (int mt = 0; mt < 2; mt++)
                ldm4(a[mt], aBase + (uint32_t)(arow[mt] * HP + kb + akoff) * 2);
            uint32_t b[8][2];
            #pragma unroll
            for (int q = 0; q < 4; q++) {
                uint32_t r[4];
                ldm4(r, bBase + (uint32_t)(brow[q] * HP + kb + bkoff) * 2);
                b[2 * q][0] = r[0]; b[2 * q][1] = r[1];
                b[2 * q + 1][0] = r[2]; b[2 * q + 1][1] = r[3];
            }
            #pragma unroll
            for (int mt = 0; mt < 2; mt++)
                #pragma unroll
                for (int nt = 0; nt < 8; nt++)
                    mma16(acc[mt][nt], a[mt], b[nt]);
        }
    }

    int cb = c4 * 2;
    if (MODE == 0) {
        __half* oph = (__half*)outp;
        #pragma unroll
        for (int mt = 0; mt < 2; mt++)
            #pragma unroll
            for (int half = 0; half < 2; half++) {
                int m = m0 + wm + mt * 16 + r4 + half * 8;
                __half* dst = oph + (size_t)m * QKVC;
                #pragma unroll
                for (int nt = 0; nt < 8; nt++) {
                    int o = n0 + wn + nt * 8 + cb;
                    // head-interleaved remap
                    int which = (o >= 768) ? 2 : ((o >= 384) ? 1 : 0);
                    int c = o - which * 384;
                    int noff = (c >> 5) * 96 + which * 32 + (c & 31);
                    *(__half2*)(dst + noff) = __floats2half2_rn(
                        acc[mt][nt][half * 2 + 0] + biasptr[o],
                        acc[mt][nt][half * 2 + 1] + biasptr[o + 1]);
                }
            }
    } else {
        float* opf = (float*)outp;
        int b = m0 >> 14;
        int ppb = m0 & (HWPIX - 1);
        #pragma unroll
        for (int mt = 0; mt < 2; mt++)
            #pragma unroll
            for (int half = 0; half < 2; half++) {
                int pp = ppb + wm + mt * 16 + r4 + half * 8;
                #pragma unroll
                for (int nt = 0; nt < 8; nt++)
                    #pragma unroll
                    for (int j = 0; j < 2; j++) {
                        int o = n0 + wn + nt * 8 + cb + j;
                        opf[((size_t)(b * CDIM + o)) * HWPIX + pp] =
                            acc[mt][nt][half * 2 + j] + biasptr[o];
                    }
            }
    }
}

// =================================================================
// PDSCA helpers on half tiles (pitch 40 halves per token row)
// =================================================================
__device__ __forceinline__ void ld8h(const __half* base, float* r) {
    union { int4 i; __half2 h[4]; } u;
    u.i = *(const int4*)base;
    float2 f0 = __half22float2(u.h[0]), f1 = __half22float2(u.h[1]);
    float2 f2 = __half22float2(u.h[2]), f3 = __half22float2(u.h[3]);
    r[0] = f0.x; r[1] = f0.y; r[2] = f1.x; r[3] = f1.y;
    r[4] = f2.x; r[5] = f2.y; r[6] = f3.x; r[7] = f3.y;
}

__device__ __forceinline__ void conv33h(
        const __half* xs, const float* __restrict__ dw_w,
        const float* __restrict__ dw_b, int it, float* o8) {
    int c = it >> 3, sy = it & 7;
    float rm[10], rc[10], rp[10];
    #pragma unroll
    for (int i = 0; i < 10; i++) { rm[i] = 0.f; rc[i] = 0.f; rp[i] = 0.f; }
    ld8h(xs + (2 * c + (sy >> 2)) * 40 + (sy & 3) * 8, rc + 1);
    if (sy > 0) {
        int r = sy - 1;
        ld8h(xs + (2 * c + (r >> 2)) * 40 + (r & 3) * 8, rm + 1);
    }
    if (sy < 7) {
        int r = sy + 1;
        ld8h(xs + (2 * c + (r >> 2)) * 40 + (r & 3) * 8, rp + 1);
    }
    const float* wp = dw_w + c * 9;
    float w0 = wp[0], w1 = wp[1], w2 = wp[2];
    float w3 = wp[3], w4 = wp[4], w5 = wp[5];
    float w6 = wp[6], w7 = wp[7], w8 = wp[8];
    float bias = dw_b[c];
    #pragma unroll
    for (int ix = 0; ix < 8; ix++) {
        float s = bias;
        s += w0 * rm[ix] + w1 * rm[ix + 1] + w2 * rm[ix + 2];
        s += w3 * rc[ix] + w4 * rc[ix + 1] + w5 * rc[ix + 2];
        s += w6 * rp[ix] + w7 * rp[ix + 1] + w8 * rp[ix + 2];
        o8[ix] = s;
    }
}

__device__ __forceinline__ void gate_apply_h(
        __half* xs, const float* o8, float cav, int it) {
    int c = it >> 3, sy = it & 7;
    __half* base = xs + (2 * c + (sy >> 2)) * 40 + (sy & 3) * 8;
    float xv[8];
    ld8h(base, xv);
    union { int4 i; __half2 h[4]; } u;
    #pragma unroll
    for (int p = 0; p < 4; p++) {
        float g0 = 1.0f / (1.0f + __expf(-(o8[2 * p] + cav)));
        float g1 = 1.0f / (1.0f + __expf(-(o8[2 * p + 1] + cav)));
        u.h[p] = __floats2half2_rn(xv[2 * p] * g0, xv[2 * p + 1] * g1);
    }
    *(int4*)base = u.i;
}

// =================================================================
// per-(window, head) merged PDSCA(Q,K) + attention — all-fp16 tiles
// =================================================================
__global__ void __launch_bounds__(128) attn_kernel(
        const float* __restrict__ log_temp,
        const float* __restrict__ pqw,  const float* __restrict__ pqb,
        const float* __restrict__ pqf1w, const float* __restrict__ pqf1b,
        const float* __restrict__ pqf2w, const float* __restrict__ pqf2b,
        const float* __restrict__ pkw,  const float* __restrict__ pkb,
        const float* __restrict__ pkf1w, const float* __restrict__ pkf1b,
        const float* __restrict__ pkf2w, const float* __restrict__ pkf2b) {
    __shared__ __align__(16) __half qsh[NTOK * 40];
    __shared__ __align__(16) __half ksh[NTOK * 40];
    __shared__ __align__(16) __half vsTh[HD * 72];
    __shared__ __align__(16) __half ath[NTOK * 72];
    __shared__ float gapq[32], gapk[32], hidq[8], hidk[8], caq[32], cak[32];

    int bi  = blockIdx.x;
    int win = bi / HEADS;
    int h   = bi - win * HEADS;
    int t   = threadIdx.x;
    int b   = win >> 8, hb = (win >> 4) & 15, wb = win & 15;
    int pbase = b * HWPIX + hb * 8 * WDIM + wb * 8;

    // ---- fully-coalesced load from head-interleaved layout ----
    for (int idx = t; idx < 768; idx += 128) {
        int n = idx / 12, rem = idx - n * 12;
        int which = rem >> 2, d8 = (rem & 3) * 8;
        int p = pbase + (n >> 3) * WDIM + (n & 7);
        const __half* src = g_qkvh + (size_t)p * QKVC + h * 96 + rem * 8;
        int4 v = *(const int4*)src;
        if (which == 0) {
            *(int4*)&qsh[n * 40 + d8] = v;
        } else if (which == 1) {
            *(int4*)&ksh[n * 40 + d8] = v;
        } else {
            union { int4 i; __half hh[8]; } u; u.i = v;
            #pragma unroll
            for (int i = 0; i < 8; i++)
                vsTh[(d8 + i) * 72 + n] = u.hh[i];
        }
    }
    __syncthreads();

    float ocq[2][8], ock[2][8];
    conv33h(qsh, pqw, pqb, t, ocq[0]);
    conv33h(qsh, pqw, pqb, t + 128, ocq[1]);
    conv33h(ksh, pkw, pkb, t, ock[0]);
    conv33h(ksh, pkw, pkb, t + 128, ock[1]);
    if (t < 32) {
        float r0[8], r1[8], s = 0.f;
        #pragma unroll
        for (int i = 0; i < 4; i++) {
            ld8h(qsh + (2 * t) * 40 + i * 8, r0);
            ld8h(qsh + (2 * t + 1) * 40 + i * 8, r1);
            #pragma unroll
            for (int j = 0; j < 8; j++) s += r0[j] + r1[j];
        }
        gapq[t] = s * (1.0f / 64.0f);
    } else if (t >= 64 && t < 96) {
        int c = t - 64;
        float r0[8], r1[8], s = 0.f;
        #pragma unroll
        for (int i = 0; i < 4; i++) {
            ld8h(ksh + (2 * c) * 40 + i * 8, r0);
            ld8h(ksh + (2 * c + 1) * 40 + i * 8, r1);
            #pragma unroll
            for (int j = 0; j < 8; j++) s += r0[j] + r1[j];
        }
        gapk[c] = s * (1.0f / 64.0f);
    }
    __syncthreads();
    if (t < 8) {
        float s = pqf1b[t];
        #pragma unroll
        for (int c = 0; c < 32; c++) s += gapq[c] * pqf1w[t * 32 + c];
        hidq[t] = fmaxf(s, 0.f);
    } else if (t >= 64 && t < 72) {
        int u = t - 64;
        float s = pkf1b[u];
        #pragma unroll
        for (int c = 0; c < 32; c++) s += gapk[c] * pkf1w[u * 32 + c];
        hidk[u] = fmaxf(s, 0.f);
    }
    __syncthreads();
    if (t < 32) {
        float s = pqf2b[t];
        #pragma unroll
        for (int j = 0; j < 8; j++) s += hidq[j] * pqf2w[t * 8 + j];
        caq[t] = s;
    } else if (t >= 64 && t < 96) {
        int c = t - 64;
        float s = pkf2b[c];
        #pragma unroll
        for (int j = 0; j < 8; j++) s += hidk[j] * pkf2w[c * 8 + j];
        cak[c] = s;
    }
    __syncthreads();
    gate_apply_h(qsh, ocq[0], caq[t >> 3], t);
    gate_apply_h(qsh, ocq[1], caq[(t + 128) >> 3], t + 128);
    gate_apply_h(ksh, ock[0], cak[t >> 3], t);
    gate_apply_h(ksh, ock[1], cak[(t + 128) >> 3], t + 128);
    __syncthreads();

    int lane = t & 31, w = t >> 5;
    int r4 = lane >> 2, c4 = lane & 3;
    int m0 = w * 16;
    int lr = lane & 7, g = lane >> 3;
    int arow = m0 + (g & 1) * 8 + lr;
    int akoff = (g >> 1) * 8;
    int bkoff = (g & 1) * 8;
    uint32_t qB = smem_u32(qsh), kB = smem_u32(ksh);
    uint32_t vB = smem_u32(vsTh), pB = smem_u32(ath);

    float sacc[8][4];
    #pragma unroll
    for (int nt = 0; nt < 8; nt++)
        #pragma unroll
        for (int j = 0; j < 4; j++) sacc[nt][j] = 0.f;

    #pragma unroll
    for (int kk = 0; kk < 2; kk++) {
        int kb = kk * 16;
        uint32_t a[4];
        ldm4(a, qB + (uint32_t)(arow * 40 + kb + akoff) * 2);
        #pragma unroll
        for (int q = 0; q < 4; q++) {
            int nrow = (2 * q + (g >> 1)) * 8 + lr;
            uint32_t r[4];
            ldm4(r, kB + (uint32_t)(nrow * 40 + kb + bkoff) * 2);
            mma16(sacc[2 * q], a, r);
            mma16(sacc[2 * q + 1], a, r + 2);
        }
    }

    float temp = __expf(log_temp[0]);
    const float* brow2 = g_bias + h * 225;
    int r_lo = m0 + r4, r_hi = r_lo + 8;
    int ylo = r_lo >> 3, xlo = r_lo & 7;
    int yhi = r_hi >> 3, xhi = r_hi & 7;

    float mlo = -1e30f, mhi = -1e30f;
    #pragma unroll
    for (int nt = 0; nt < 8; nt++)
        #pragma unroll
        for (int j = 0; j < 2; j++) {
            int col = nt * 8 + 2 * c4 + j;
            int cy = col >> 3, cx = col & 7;
            float blo = brow2[(ylo - cy + 7) * 15 + (xlo - cx + 7)];
            float bhi = brow2[(yhi - cy + 7) * 15 + (xhi - cx + 7)];
            sacc[nt][j]     = sacc[nt][j] * temp + blo;
            sacc[nt][2 + j] = sacc[nt][2 + j] * temp + bhi;
            mlo = fmaxf(mlo, sacc[nt][j]);
            mhi = fmaxf(mhi, sacc[nt][2 + j]);
        }
    mlo = fmaxf(mlo, __shfl_xor_sync(0xffffffffu, mlo, 1));
    mlo = fmaxf(mlo, __shfl_xor_sync(0xffffffffu, mlo, 2));
    mhi = fmaxf(mhi, __shfl_xor_sync(0xffffffffu, mhi, 1));
    mhi = fmaxf(mhi, __shfl_xor_sync(0xffffffffu, mhi, 2));

    float slo = 0.f, shi = 0.f;
    #pragma unroll
    for (int nt = 0; nt < 8; nt++)
        #pragma unroll
        for (int j = 0; j < 2; j++) {
            float e0 = __expf(sacc[nt][j] - mlo);
            float e1 = __expf(sacc[nt][2 + j] - mhi);
            sacc[nt][j] = e0; sacc[nt][2 + j] = e1;
            slo += e0; shi += e1;
        }
    slo += __shfl_xor_sync(0xffffffffu, slo, 1);
    slo += __shfl_xor_sync(0xffffffffu, slo, 2);
    shi += __shfl_xor_sync(0xffffffffu, shi, 1);
    shi += __shfl_xor_sync(0xffffffffu, shi, 2);
    float ilo = 1.0f / slo, ihi = 1.0f / shi;

    #pragma unroll
    for (int nt = 0; nt < 8; nt++) {
        int col = nt * 8 + 2 * c4;
        *(__half2*)&ath[r_lo * 72 + col] =
            __floats2half2_rn(sacc[nt][0] * ilo, sacc[nt][1] * ilo);
        *(__half2*)&ath[r_hi * 72 + col] =
            __floats2half2_rn(sacc[nt][2] * ihi, sacc[nt][3] * ihi);
    }
    __syncwarp();

    float oacc[4][4];
    #pragma unroll
    for (int nt = 0; nt < 4; nt++)
        #pragma unroll
        for (int j = 0; j < 4; j++) oacc[nt][j] = 0.f;

    #pragma unroll
    for (int kk = 0; kk < 4; kk++) {
        int kb = kk * 16;
        uint32_t a[4];
        ldm4(a, pB + (uint32_t)(arow * 72 + kb + akoff) * 2);
        #pragma unroll
        for (int q = 0; q < 2; q++) {
            int nrow = (2 * q + (g >> 1)) * 8 + lr;
            uint32_t r[4];
            ldm4(r, vB + (uint32_t)(nrow * 72 + kb + bkoff) * 2);
            mma16(oacc[2 * q], a, r);
            mma16(oacc[2 * q + 1], a, r + 2);
        }
    }

    #pragma unroll
    for (int half = 0; half < 2; half++) {
        int row = (half == 0) ? r_lo : r_hi;
        int p = pbase + (row >> 3) * WDIM + (row & 7);
        __half2* dst = (__half2*)(g_aoh + (size_t)p * CDIM + h * HD);
        #pragma unroll
        for (int nt = 0; nt < 4; nt++)
            dst[(nt * 8 + 2 * c4) >> 1] =
                __floats2half2_rn(oacc[nt][half * 2 + 0], oacc[nt][half * 2 + 1]);
    }
}

// =================================================================
// launch
// =================================================================
extern "C" void kernel_launch(void* const* d_in, const int* in_sizes, int n_in,
                              void* d_out, int out_size) {
    const float* x        = (const float*)d_in[0];
    const float* w_qk     = (const float*)d_in[1];
    const float* b_qk     = (const float*)d_in[2];
    const float* w_v      = (const float*)d_in[3];
    const float* b_v      = (const float*)d_in[4];
    const float* log_temp = (const float*)d_in[5];
    const float* pq_dw_w  = (const float*)d_in[6];
    const float* pq_dw_b  = (const float*)d_in[7];
    const float* pq_f1w   = (const float*)d_in[8];
    const float* pq_f1b   = (const float*)d_in[9];
    const float* pq_f2w   = (const float*)d_in[10];
    const float* pq_f2b   = (const float*)d_in[11];
    const float* pk_dw_w  = (const float*)d_in[12];
    const float* pk_dw_b  = (const float*)d_in[13];
    const float* pk_f1w   = (const float*)d_in[14];
    const float* pk_f1b   = (const float*)d_in[15];
    const float* pk_f2w   = (const float*)d_in[16];
    const float* pk_f2b   = (const float*)d_in[17];
    const float* pos_w    = (const float*)d_in[18];
    const float* pos_sc   = (const float*)d_in[20];
    const float* meta_w1  = (const float*)d_in[21];
    const float* meta_b1  = (const float*)d_in[22];
    const float* meta_w2  = (const float*)d_in[23];
    const float* meta_b2  = (const float*)d_in[24];
    const float* w_po     = (const float*)d_in[25];
    const float* w_proj   = (const float*)d_in[26];
    const float* b_proj   = (const float*)d_in[27];
    float* out = (float*)d_out;

    cudaFuncSetAttribute(gemm_mma<0>, cudaFuncAttributeMaxDynamicSharedMemorySize, GEMM_SMEM);
    cudaFuncSetAttribute(gemm_mma<1>, cudaFuncAttributeMaxDynamicSharedMemorySize, GEMM_SMEM);

    prep_kernel<<<NB_PREP, 256>>>(x, w_qk, b_qk, w_v, b_v, w_proj, w_po,
                                  pos_w, pos_sc, meta_w1, meta_b1, meta_w2, meta_b2);

    {
        const __half* A; cudaGetSymbolAddress((void**)&A, g_xTh);
        const __half* Bp; cudaGetSymbolAddress((void**)&Bp, g_wbh);
        const float* bb; cudaGetSymbolAddress((void**)&bb, g_bqkv);
        void* op; cudaGetSymbolAddress(&op, g_qkvh);
        gemm_mma<0><<<dim3(QKVC / 128, NPIX / 128), 256, GEMM_SMEM>>>(A, Bp, bb, op);
    }

    attn_kernel<<<NWIN * HEADS, 128>>>(log_temp,
        pq_dw_w, pq_dw_b, pq_f1w, pq_f1b, pq_f2w, pq_f2b,
        pk_dw_w, pk_dw_b, pk_f1w, pk_f1b, pk_f2w, pk_f2b);

    {
        const __half* A; cudaGetSymbolAddress((void**)&A, g_aoh);
        const __half* Bp; cudaGetSymbolAddress((void**)&Bp, g_Wch);
        gemm_mma<1><<<dim3(CDIM / 128, NPIX / 128), 256, GEMM_SMEM>>>(A, Bp, b_proj, (void*)out);
    }
}

// round 16
// speedup vs baseline: 1.1167x; 1.1167x over previous
#include <cuda_runtime.h>
#include <cuda_fp16.h>
#include <cstdint>
#include <math.h>

// ---------------- problem constants ----------------
#define BATCH 4
#define CDIM  384
#define HDIM  128
#define WDIM  128
#define HWPIX 16384
#define NPIX  65536
#define HEADS 12
#define HD    32
#define WS    8
#define NTOK  64
#define NWIN  1024
#define QKVC  1152

// ---------------- device scratch ----------------
__device__ __half g_qkvh[(size_t)NPIX * QKVC];   // per-pixel [q(384) k(384) v(384)]
__device__ __half g_aoh[(size_t)NPIX * CDIM];
__device__ __half g_xTh[(size_t)NPIX * CDIM];
__device__ __half g_wbh[QKVC * CDIM];
__device__ float  g_bqkv[QKVC];
__device__ float  g_bias[HEADS * 225];
__device__ __half g_Wch[CDIM * CDIM];

// ---------------- helpers ----------------
__device__ __forceinline__ uint32_t smem_u32(const void* p) {
    uint32_t a;
    asm("{ .reg .u64 t; cvta.to.shared.u64 t, %1; cvt.u32.u64 %0, t; }" : "=r"(a) : "l"(p));
    return a;
}
__device__ __forceinline__ void cp16(uint32_t saddr, const void* g) {
    asm volatile("cp.async.cg.shared.global [%0], [%1], 16;" :: "r"(saddr), "l"(g));
}
#define CP_COMMIT() asm volatile("cp.async.commit_group;" ::: "memory")
#define CP_WAIT0()  asm volatile("cp.async.wait_group 0;" ::: "memory")
#define CP_WAIT1()  asm volatile("cp.async.wait_group 1;" ::: "memory")

__device__ __forceinline__ void ldm4(uint32_t* r, uint32_t addr) {
    asm volatile("ldmatrix.sync.aligned.m8n8.x4.shared.b16 {%0,%1,%2,%3}, [%4];"
        : "=r"(r[0]), "=r"(r[1]), "=r"(r[2]), "=r"(r[3]) : "r"(addr));
}

__device__ __forceinline__ void mma16(float* c, const uint32_t* a, const uint32_t* b) {
    asm volatile(
        "mma.sync.aligned.m16n8k16.row.col.f32.f16.f16.f32 "
        "{%0,%1,%2,%3}, {%4,%5,%6,%7}, {%8,%9}, {%0,%1,%2,%3};"
        : "+f"(c[0]), "+f"(c[1]), "+f"(c[2]), "+f"(c[3])
        : "r"(a[0]), "r"(a[1]), "r"(a[2]), "r"(a[3]),
          "r"(b[0]), "r"(b[1]));
}

// =================================================================
// unified prep kernel: xpose | wprep | wc | bias, 256 threads
// =================================================================
#define NB_XPOSE (512 * 12 * 4)
#define NB_WPREP ((QKVC * CDIM) / 256)
#define NB_WC    ((CDIM * CDIM) / 256)
#define NB_BIAS  225
#define NB_PREP  (NB_XPOSE + NB_WPREP + NB_WC + NB_BIAS)

__global__ void __launch_bounds__(256) prep_kernel(
        const float* __restrict__ x,
        const float* __restrict__ w_qk, const float* __restrict__ b_qk,
        const float* __restrict__ w_v,  const float* __restrict__ b_v,
        const float* __restrict__ w_proj, const float* __restrict__ w_po,
        const float* __restrict__ pcw, const float* __restrict__ psc,
        const float* __restrict__ mw1, const float* __restrict__ mb1,
        const float* __restrict__ mw2, const float* __restrict__ mb2) {
    __shared__ __align__(16) float tile[32][33];
    __shared__ __align__(16) float rel[CDIM];
    __shared__ __align__(16) float hid[128];
    __shared__ float part[256];
    int blk = blockIdx.x;
    int t = threadIdx.x;

    if (blk < NB_XPOSE) {
        int bx = blk & 511, by = (blk >> 9) % 12, bz = blk / (512 * 12);
        int tx = t & 31, ty = t >> 5;
        const float* src = x + ((size_t)(bz * CDIM + by * 32)) * HWPIX + bx * 32;
        #pragma unroll
        for (int i = 0; i < 32; i += 8)
            tile[ty + i][tx] = src[(size_t)(ty + i) * HWPIX + tx];
        __syncthreads();
        __half* dst = g_xTh + ((size_t)(bz * HWPIX + bx * 32)) * CDIM + by * 32;
        #pragma unroll
        for (int i = 0; i < 32; i += 8)
            dst[(size_t)(ty + i) * CDIM + tx] = __float2half_rn(tile[tx][ty + i]);
        return;
    }
    blk -= NB_XPOSE;
    if (blk < NB_WPREP) {
        int i = blk * 256 + t;
        float v = (i < 2 * CDIM * CDIM) ? w_qk[i] : w_v[i - 2 * CDIM * CDIM];
        g_wbh[i] = __float2half_rn(v);
        if (i < QKVC)
            g_bqkv[i] = (i < 2 * CDIM) ? b_qk[i] : b_v[i - 2 * CDIM];
        return;
    }
    blk -= NB_WPREP;
    if (blk < NB_WC) {
        int idx = blk * 256 + t;
        int o = idx / CDIM, c = idx - o * CDIM;
        const float* pr = w_proj + o * CDIM;
        float a0 = 0.f, a1 = 0.f, a2 = 0.f, a3 = 0.f;
        for (int k = 0; k < CDIM; k += 4) {
            a0 += pr[k] * w_po[k * CDIM + c];
            a1 += pr[k + 1] * w_po[(k + 1) * CDIM + c];
            a2 += pr[k + 2] * w_po[(k + 2) * CDIM + c];
            a3 += pr[k + 3] * w_po[(k + 3) * CDIM + c];
        }
        g_Wch[o * CDIM + c] = __float2half_rn((a0 + a1) + (a2 + a3));
        return;
    }
    blk -= NB_WC;
    {
        int idx = blk;
        float dx = (float)((idx % 15) - 7) * (2.0f / 7.0f);
        float dy = (float)((idx / 15) - 7) * (2.0f / 7.0f);
        int u = t & 127, hv2 = t >> 7;
        float sc = psc[0];
        for (int c = t; c < CDIM; c += 256)
            rel[c] = sc * (pcw[2 * c] * dx + pcw[2 * c + 1] * dy);
        __syncthreads();
        {
            float a0 = 0.f, a1 = 0.f, a2 = 0.f, a3 = 0.f;
            const float4* w = (const float4*)(mw1 + u * CDIM + hv2 * 192);
            const float4* r = (const float4*)(rel + hv2 * 192);
            #pragma unroll 4
            for (int c = 0; c < 48; c++) {
                float4 wv = w[c], rv = r[c];
                a0 += wv.x * rv.x; a1 += wv.y * rv.y;
                a2 += wv.z * rv.z; a3 += wv.w * rv.w;
            }
            part[t] = (a0 + a1) + (a2 + a3);
        }
        __syncthreads();
        if (t < 128) {
            float s = mb1[t] + part[t] + part[t + 128];
            hid[t] = 0.5f * s * (1.0f + erff(s * 0.70710678118654752f));
        }
        __syncthreads();
        if (t < HEADS) {
            float a0 = 0.f, a1 = 0.f, a2 = 0.f, a3 = 0.f;
            const float4* w2 = (const float4*)(mw2 + t * 128);
            const float4* hh = (const float4*)hid;
            #pragma unroll 4
            for (int j = 0; j < 32; j++) {
                float4 wv = w2[j], hvv = hh[j];
                a0 += wv.x * hvv.x; a1 += wv.y * hvv.y;
                a2 += wv.z * hvv.z; a3 += wv.w * hvv.w;
            }
            g_bias[t * 225 + idx] = mb2[t] + (a0 + a1) + (a2 + a3);
        }
    }
}

// =================================================================
// fp16 mma.sync GEMM with ldmatrix, 3-stage cp.async pipeline
// =================================================================
#define HP     72
#define KCH    64
#define NCH    6
#define NSTAGE 3
#define STAGE_H (2 * 128 * HP)
#define GEMM_SMEM (NSTAGE * STAGE_H * 2)

template <int MODE>
__global__ void __launch_bounds__(256) gemm_mma(
        const __half* __restrict__ Aptr, const __half* __restrict__ Bptr,
        const float* __restrict__ biasptr, void* __restrict__ outp) {
    extern __shared__ __align__(16) __half smh[];

    int tid = threadIdx.x;
    int n0 = blockIdx.x * 128;
    int m0 = blockIdx.y * 128;
    int lane = tid & 31, wid = tid >> 5;
    int wm = (wid & 3) * 32;
    int wn = (wid >> 2) * 64;

    const __half* Arow = Aptr + (size_t)m0 * CDIM;
    const __half* Brow = Bptr + (size_t)n0 * CDIM;
    uint32_t aU[NSTAGE], bU[NSTAGE];
    #pragma unroll
    for (int s = 0; s < NSTAGE; s++) {
        aU[s] = smem_u32(smh + s * STAGE_H);
        bU[s] = smem_u32(smh + s * STAGE_H + 128 * HP);
    }

    int ldrow = tid >> 3, ldseg = tid & 7;
    auto load_chunk = [&](int k0, int s) {
        #pragma unroll
        for (int i = 0; i < 4; i++) {
            int row = ldrow + i * 32;
            uint32_t so = (uint32_t)(row * HP + ldseg * 8) * 2;
            cp16(aU[s] + so, Arow + (size_t)row * CDIM + k0 + ldseg * 8);
            cp16(bU[s] + so, Brow + (size_t)row * CDIM + k0 + ldseg * 8);
        }
        CP_COMMIT();
    };

    float acc[2][8][4];
    #pragma unroll
    for (int mt = 0; mt < 2; mt++)
        #pragma unroll
        for (int nt = 0; nt < 8; nt++)
            #pragma unroll
            for (int j = 0; j < 4; j++) acc[mt][nt][j] = 0.f;

    load_chunk(0, 0);
    load_chunk(KCH, 1);

    int lr = lane & 7, g = lane >> 3;
    int arow[2];
    arow[0] = wm + (g & 1) * 8 + lr;
    arow[1] = wm + 16 + (g & 1) * 8 + lr;
    int akoff = (g >> 1) * 8;
    int brow[4];
    #pragma unroll
    for (int q = 0; q < 4; q++)
        brow[q] = wn + (2 * q + (g >> 1)) * 8 + lr;
    int bkoff = (g & 1) * 8;

    int r4 = lane >> 2, c4 = lane & 3;
    for (int i = 0; i < NCH; i++) {
        if (i + 1 < NCH) CP_WAIT1(); else CP_WAIT0();
        __syncthreads();
        if (i + 2 < NCH) load_chunk((i + 2) * KCH, (i + 2) % NSTAGE);
        int s = i % NSTAGE;
        uint32_t aBase = aU[s];
        uint32_t bBase = bU[s];
        #pragma unroll
        for (int kk = 0; kk < 4; kk++) {
            int kb = kk * 16;
            uint32_t a[2][4];
            #pragma unroll
            for (int mt = 0; mt < 2; mt++)
                ldm4(a[mt], aBase + (uint32_t)(arow[mt] * HP + kb + akoff) * 2);
            uint32_t b[8][2];
            #pragma unroll
            for (int q = 0; q < 4; q++) {
                uint32_t r[4];
                ldm4(r, bBase + (uint32_t)(brow[q] * HP + kb + bkoff) * 2);
                b[2 * q][0] = r[0]; b[2 * q][1] = r[1];
                b[2 * q + 1][0] = r[2]; b[2 * q + 1][1] = r[3];
            }
            #pragma unroll
            for (int mt = 0; mt < 2; mt++)
                #pragma unroll
                for (int nt = 0; nt < 8; nt++)
                    mma16(acc[mt][nt], a[mt], b[nt]);
        }
    }

    int cb = c4 * 2;
    if (MODE == 0) {
        __half* oph = (__half*)outp;
        #pragma unroll
        for (int mt = 0; mt < 2; mt++)
            #pragma unroll
            for (int half = 0; half < 2; half++) {
                int m = m0 + wm + mt * 16 + r4 + half * 8;
                __half* dst = oph + (size_t)m * QKVC + n0 + wn;
                #pragma unroll
                for (int nt = 0; nt < 8; nt++) {
                    int o = n0 + wn + nt * 8 + cb;
                    *(__half2*)(dst + nt * 8 + cb) = __floats2half2_rn(
                        acc[mt][nt][half * 2 + 0] + biasptr[o],
                        acc[mt][nt][half * 2 + 1] + biasptr[o + 1]);
                }
            }
    } else {
        float* opf = (float*)outp;
        int b = m0 >> 14;
        int ppb = m0 & (HWPIX - 1);
        #pragma unroll
        for (int mt = 0; mt < 2; mt++)
            #pragma unroll
            for (int half = 0; half < 2; half++) {
                int pp = ppb + wm + mt * 16 + r4 + half * 8;
                #pragma unroll
                for (int nt = 0; nt < 8; nt++)
                    #pragma unroll
                    for (int j = 0; j < 2; j++) {
                        int o = n0 + wn + nt * 8 + cb + j;
                        opf[((size_t)(b * CDIM + o)) * HWPIX + pp] =
                            acc[mt][nt][half * 2 + j] + biasptr[o];
                    }
            }
    }
}

// =================================================================
// PDSCA helpers on half tiles (pitch 40 halves per token row)
// =================================================================
__device__ __forceinline__ void ld8h(const __half* base, float* r) {
    union { int4 i; __half2 h[4]; } u;
    u.i = *(const int4*)base;
    float2 f0 = __half22float2(u.h[0]), f1 = __half22float2(u.h[1]);
    float2 f2 = __half22float2(u.h[2]), f3 = __half22float2(u.h[3]);
    r[0] = f0.x; r[1] = f0.y; r[2] = f1.x; r[3] = f1.y;
    r[4] = f2.x; r[5] = f2.y; r[6] = f3.x; r[7] = f3.y;
}

__device__ __forceinline__ void conv33h(
        const __half* xs, const float* __restrict__ dw_w,
        const float* __restrict__ dw_b, int it, float* o8) {
    int c = it >> 3, sy = it & 7;
    float rm[10], rc[10], rp[10];
    #pragma unroll
    for (int i = 0; i < 10; i++) { rm[i] = 0.f; rc[i] = 0.f; rp[i] = 0.f; }
    ld8h(xs + (2 * c + (sy >> 2)) * 40 + (sy & 3) * 8, rc + 1);
    if (sy > 0) {
        int r = sy - 1;
        ld8h(xs + (2 * c + (r >> 2)) * 40 + (r & 3) * 8, rm + 1);
    }
    if (sy < 7) {
        int r = sy + 1;
        ld8h(xs + (2 * c + (r >> 2)) * 40 + (r & 3) * 8, rp + 1);
    }
    const float* wp = dw_w + c * 9;
    float w0 = wp[0], w1 = wp[1], w2 = wp[2];
    float w3 = wp[3], w4 = wp[4], w5 = wp[5];
    float w6 = wp[6], w7 = wp[7], w8 = wp[8];
    float bias = dw_b[c];
    #pragma unroll
    for (int ix = 0; ix < 8; ix++) {
        float s = bias;
        s += w0 * rm[ix] + w1 * rm[ix + 1] + w2 * rm[ix + 2];
        s += w3 * rc[ix] + w4 * rc[ix + 1] + w5 * rc[ix + 2];
        s += w6 * rp[ix] + w7 * rp[ix + 1] + w8 * rp[ix + 2];
        o8[ix] = s;
    }
}

__device__ __forceinline__ void gate_apply_h(
        __half* xs, const float* o8, float cav, int it) {
    int c = it >> 3, sy = it & 7;
    __half* base = xs + (2 * c + (sy >> 2)) * 40 + (sy & 3) * 8;
    float xv[8];
    ld8h(base, xv);
    union { int4 i; __half2 h[4]; } u;
    #pragma unroll
    for (int p = 0; p < 4; p++) {
        float g0 = 1.0f / (1.0f + __expf(-(o8[2 * p] + cav)));
        float g1 = 1.0f / (1.0f + __expf(-(o8[2 * p + 1] + cav)));
        u.h[p] = __floats2half2_rn(xv[2 * p] * g0, xv[2 * p + 1] * g1);
    }
    *(int4*)base = u.i;
}

// =================================================================
// per-(window, head) merged PDSCA(Q,K) + attention — all-fp16 tiles
// =================================================================
__global__ void __launch_bounds__(128) attn_kernel(
        const float* __restrict__ log_temp,
        const float* __restrict__ pqw,  const float* __restrict__ pqb,
        const float* __restrict__ pqf1w, const float* __restrict__ pqf1b,
        const float* __restrict__ pqf2w, const float* __restrict__ pqf2b,
        const float* __restrict__ pkw,  const float* __restrict__ pkb,
        const float* __restrict__ pkf1w, const float* __restrict__ pkf1b,
        const float* __restrict__ pkf2w, const float* __restrict__ pkf2b) {
    __shared__ __align__(16) __half qsh[NTOK * 40];
    __shared__ __align__(16) __half ksh[NTOK * 40];
    __shared__ __align__(16) __half vsTh[HD * 72];
    __shared__ __align__(16) __half ath[NTOK * 72];
    __shared__ float gapq[32], gapk[32], hidq[8], hidk[8], caq[32], cak[32];

    int bi  = blockIdx.x;
    int win = bi / HEADS;
    int h   = bi - win * HEADS;
    int t   = threadIdx.x;
    int b   = win >> 8, hb = (win >> 4) & 15, wb = win & 15;
    int pbase = b * HWPIX + hb * 8 * WDIM + wb * 8;

    for (int tt = t; tt < 256; tt += 128) {
        int n = tt >> 2, d8 = (tt & 3) * 8;
        int p = pbase + (n >> 3) * WDIM + (n & 7);
        const __half* src = g_qkvh + (size_t)p * QKVC + h * HD + d8;
        int4 qi = *(const int4*)(src);
        int4 ki = *(const int4*)(src + CDIM);
        union { int4 i; __half hh[8]; } uv;
        uv.i = *(const int4*)(src + 2 * CDIM);
        *(int4*)&qsh[n * 40 + d8] = qi;
        *(int4*)&ksh[n * 40 + d8] = ki;
        #pragma unroll
        for (int i = 0; i < 8; i++)
            vsTh[(d8 + i) * 72 + n] = uv.hh[i];
    }
    __syncthreads();

    float ocq[2][8], ock[2][8];
    conv33h(qsh, pqw, pqb, t, ocq[0]);
    conv33h(qsh, pqw, pqb, t + 128, ocq[1]);
    conv33h(ksh, pkw, pkb, t, ock[0]);
    conv33h(ksh, pkw, pkb, t + 128, ock[1]);
    if (t < 32) {
        float r0[8], r1[8], s = 0.f;
        #pragma unroll
        for (int i = 0; i < 4; i++) {
            ld8h(qsh + (2 * t) * 40 + i * 8, r0);
            ld8h(qsh + (2 * t + 1) * 40 + i * 8, r1);
            #pragma unroll
            for (int j = 0; j < 8; j++) s += r0[j] + r1[j];
        }
        gapq[t] = s * (1.0f / 64.0f);
    } else if (t >= 64 && t < 96) {
        int c = t - 64;
        float r0[8], r1[8], s = 0.f;
        #pragma unroll
        for (int i = 0; i < 4; i++) {
            ld8h(ksh + (2 * c) * 40 + i * 8, r0);
            ld8h(ksh + (2 * c + 1) * 40 + i * 8, r1);
            #pragma unroll
            for (int j = 0; j < 8; j++) s += r0[j] + r1[j];
        }
        gapk[c] = s * (1.0f / 64.0f);
    }
    __syncthreads();
    if (t < 8) {
        float s = pqf1b[t];
        #pragma unroll
        for (int c = 0; c < 32; c++) s += gapq[c] * pqf1w[t * 32 + c];
        hidq[t] = fmaxf(s, 0.f);
    } else if (t >= 64 && t < 72) {
        int u = t - 64;
        float s = pkf1b[u];
        #pragma unroll
        for (int c = 0; c < 32; c++) s += gapk[c] * pkf1w[u * 32 + c];
        hidk[u] = fmaxf(s, 0.f);
    }
    __syncthreads();
    if (t < 32) {
        float s = pqf2b[t];
        #pragma unroll
        for (int j = 0; j < 8; j++) s += hidq[j] * pqf2w[t * 8 + j];
        caq[t] = s;
    } else if (t >= 64 && t < 96) {
        int c = t - 64;
        float s = pkf2b[c];
        #pragma unroll
        for (int j = 0; j < 8; j++) s += hidk[j] * pkf2w[c * 8 + j];
        cak[c] = s;
    }
    __syncthreads();
    gate_apply_h(qsh, ocq[0], caq[t >> 3], t);
    gate_apply_h(qsh, ocq[1], caq[(t + 128) >> 3], t + 128);
    gate_apply_h(ksh, ock[0], cak[t >> 3], t);
    gate_apply_h(ksh, ock[1], cak[(t + 128) >> 3], t + 128);
    __syncthreads();

    int lane = t & 31, w = t >> 5;
    int r4 = lane >> 2, c4 = lane & 3;
    int m0 = w * 16;
    int lr = lane & 7, g = lane >> 3;
    int arow = m0 + (g & 1) * 8 + lr;
    int akoff = (g >> 1) * 8;
    int bkoff = (g & 1) * 8;
    uint32_t qB = smem_u32(qsh), kB = smem_u32(ksh);
    uint32_t vB = smem_u32(vsTh), pB = smem_u32(ath);

    float sacc[8][4];
    #pragma unroll
    for (int nt = 0; nt < 8; nt++)
        #pragma unroll
        for (int j = 0; j < 4; j++) sacc[nt][j] = 0.f;

    #pragma unroll
    for (int kk = 0; kk < 2; kk++) {
        int kb = kk * 16;
        uint32_t a[4];
        ldm4(a, qB + (uint32_t)(arow * 40 + kb + akoff) * 2);
        #pragma unroll
        for (int q = 0; q < 4; q++) {
            int nrow = (2 * q + (g >> 1)) * 8 + lr;
            uint32_t r[4];
            ldm4(r, kB + (uint32_t)(nrow * 40 + kb + bkoff) * 2);
            mma16(sacc[2 * q], a, r);
            mma16(sacc[2 * q + 1], a, r + 2);
        }
    }

    float temp = __expf(log_temp[0]);
    const float* brow2 = g_bias + h * 225;
    int r_lo = m0 + r4, r_hi = r_lo + 8;
    int ylo = r_lo >> 3, xlo = r_lo & 7;
    int yhi = r_hi >> 3, xhi = r_hi & 7;

    float mlo = -1e30f, mhi = -1e30f;
    #pragma unroll
    for (int nt = 0; nt < 8; nt++)
        #pragma unroll
        for (int j = 0; j < 2; j++) {
            int col = nt * 8 + 2 * c4 + j;
            int cy = col >> 3, cx = col & 7;
            float blo = brow2[(ylo - cy + 7) * 15 + (xlo - cx + 7)];
            float bhi = brow2[(yhi - cy + 7) * 15 + (xhi - cx + 7)];
            sacc[nt][j]     = sacc[nt][j] * temp + blo;
            sacc[nt][2 + j] = sacc[nt][2 + j] * temp + bhi;
            mlo = fmaxf(mlo, sacc[nt][j]);
            mhi = fmaxf(mhi, sacc[nt][2 + j]);
        }
    mlo = fmaxf(mlo, __shfl_xor_sync(0xffffffffu, mlo, 1));
    mlo = fmaxf(mlo, __shfl_xor_sync(0xffffffffu, mlo, 2));
    mhi = fmaxf(mhi, __shfl_xor_sync(0xffffffffu, mhi, 1));
    mhi = fmaxf(mhi, __shfl_xor_sync(0xffffffffu, mhi, 2));

    float slo = 0.f, shi = 0.f;
    #pragma unroll
    for (int nt = 0; nt < 8; nt++)
        #pragma unroll
        for (int j = 0; j < 2; j++) {
            float e0 = __expf(sacc[nt][j] - mlo);
            float e1 = __expf(sacc[nt][2 + j] - mhi);
            sacc[nt][j] = e0; sacc[nt][2 + j] = e1;
            slo += e0; shi += e1;
        }
    slo += __shfl_xor_sync(0xffffffffu, slo, 1);
    slo += __shfl_xor_sync(0xffffffffu, slo, 2);
    shi += __shfl_xor_sync(0xffffffffu, shi, 1);
    shi += __shfl_xor_sync(0xffffffffu, shi, 2);
    float ilo = 1.0f / slo, ihi = 1.0f / shi;

    #pragma unroll
    for (int nt = 0; nt < 8; nt++) {
        int col = nt * 8 + 2 * c4;
        *(__half2*)&ath[r_lo * 72 + col] =
            __floats2half2_rn(sacc[nt][0] * ilo, sacc[nt][1] * ilo);
        *(__half2*)&ath[r_hi * 72 + col] =
            __floats2half2_rn(sacc[nt][2] * ihi, sacc[nt][3] * ihi);
    }
    __syncwarp();

    float oacc[4][4];
    #pragma unroll
    for (int nt = 0; nt < 4; nt++)
        #pragma unroll
        for (int j = 0; j < 4; j++) oacc[nt][j] = 0.f;

    #pragma unroll
    for (int kk = 0; kk < 4; kk++) {
        int kb = kk * 16;
        uint32_t a[4];
        ldm4(a, pB + (uint32_t)(arow * 72 + kb + akoff) * 2);
        #pragma unroll
        for (int q = 0; q < 2; q++) {
            int nrow = (2 * q + (g >> 1)) * 8 + lr;
            uint32_t r[4];
            ldm4(r, vB + (uint32_t)(nrow * 72 + kb + bkoff) * 2);
            mma16(oacc[2 * q], a, r);
            mma16(oacc[2 * q + 1], a, r + 2);
        }
    }

    #pragma unroll
    for (int half = 0; half < 2; half++) {
        int row = (half == 0) ? r_lo : r_hi;
        int p = pbase + (row >> 3) * WDIM + (row & 7);
        __half2* dst = (__half2*)(g_aoh + (size_t)p * CDIM + h * HD);
        #pragma unroll
        for (int nt = 0; nt < 4; nt++)
            dst[(nt * 8 + 2 * c4) >> 1] =
                __floats2half2_rn(oacc[nt][half * 2 + 0], oacc[nt][half * 2 + 1]);
    }
}

// =================================================================
// launch
// =================================================================
extern "C" void kernel_launch(void* const* d_in, const int* in_sizes, int n_in,
                              void* d_out, int out_size) {
    const float* x        = (const float*)d_in[0];
    const float* w_qk     = (const float*)d_in[1];
    const float* b_qk     = (const float*)d_in[2];
    const float* w_v      = (const float*)d_in[3];
    const float* b_v      = (const float*)d_in[4];
    const float* log_temp = (const float*)d_in[5];
    const float* pq_dw_w  = (const float*)d_in[6];
    const float* pq_dw_b  = (const float*)d_in[7];
    const float* pq_f1w   = (const float*)d_in[8];
    const float* pq_f1b   = (const float*)d_in[9];
    const float* pq_f2w   = (const float*)d_in[10];
    const float* pq_f2b   = (const float*)d_in[11];
    const float* pk_dw_w  = (const float*)d_in[12];
    const float* pk_dw_b  = (const float*)d_in[13];
    const float* pk_f1w   = (const float*)d_in[14];
    const float* pk_f1b   = (const float*)d_in[15];
    const float* pk_f2w   = (const float*)d_in[16];
    const float* pk_f2b   = (const float*)d_in[17];
    const float* pos_w    = (const float*)d_in[18];
    const float* pos_sc   = (const float*)d_in[20];
    const float* meta_w1  = (const float*)d_in[21];
    const float* meta_b1  = (const float*)d_in[22];
    const float* meta_w2  = (const float*)d_in[23];
    const float* meta_b2  = (const float*)d_in[24];
    const float* w_po     = (const float*)d_in[25];
    const float* w_proj   = (const float*)d_in[26];
    const float* b_proj   = (const float*)d_in[27];
    float* out = (float*)d_out;

    cudaFuncSetAttribute(gemm_mma<0>, cudaFuncAttributeMaxDynamicSharedMemorySize, GEMM_SMEM);
    cudaFuncSetAttribute(gemm_mma<1>, cudaFuncAttributeMaxDynamicSharedMemorySize, GEMM_SMEM);

    prep_kernel<<<NB_PREP, 256>>>(x, w_qk, b_qk, w_v, b_v, w_proj, w_po,
                                  pos_w, pos_sc, meta_w1, meta_b1, meta_w2, meta_b2);

    {
        const __half* A; cudaGetSymbolAddress((void**)&A, g_xTh);
        const __half* Bp; cudaGetSymbolAddress((void**)&Bp, g_wbh);
        const float* bb; cudaGetSymbolAddress((void**)&bb, g_bqkv);
        void* op; cudaGetSymbolAddress(&op, g_qkvh);
        gemm_mma<0><<<dim3(QKVC / 128, NPIX / 128), 256, GEMM_SMEM>>>(A, Bp, bb, op);
    }

    attn_kernel<<<NWIN * HEADS, 128>>>(log_temp,
        pq_dw_w, pq_dw_b, pq_f1w, pq_f1b, pq_f2w, pq_f2b,
        pk_dw_w, pk_dw_b, pk_f1w, pk_f1b, pk_f2w, pk_f2b);

    {
        const __half* A; cudaGetSymbolAddress((void**)&A, g_aoh);
        const __half* Bp; cudaGetSymbolAddress((void**)&Bp, g_Wch);
        gemm_mma<1><<<dim3(CDIM / 128, NPIX / 128), 256, GEMM_SMEM>>>(A, Bp, b_proj, (void*)out);
    }
}